// round 6
// baseline (speedup 1.0000x reference)
#include <cuda_runtime.h>
#include <cuda_bf16.h>
#include <cstdint>

// ---------------- problem constants ----------------
#define D_IN    4096
#define D_OUT   64
#define N_B     32
#define N_S     2048
#define N_LORA  16

#define TILE_M    256
#define NTHREADS  256
#define N_KCHUNK  (D_IN / 16)        // 256 k16 chunks
#define CPS       4                  // chunks per smem stage
#define N_STAGE   (N_KCHUNK / CPS)   // 64
#define STAGE_U4  (CPS * 256)        // 1024 uint4 per stage
#define STAGE_BYTES (STAGE_U4 * 16)  // 16 KB
#define SMEM_TOTAL  (2 * STAGE_BYTES)

// ---------------- weight scratch: fragment-layout bf16 hi/lo ----------------
// [lora][kchunk(256)][ntile(8)*32 + lane] -> uint4 {bhi0, bhi1, blo0, blo1}
__device__ __align__(16) uint4 g_wfrag[(size_t)N_LORA * 256 * 256];

// ---------------- helpers ----------------
__device__ __forceinline__ uint32_t smem_u32(const void* p) {
    uint32_t a;
    asm("{ .reg .u64 t; cvta.to.shared.u64 t, %1; cvt.u32.u64 %0, t; }" : "=r"(a) : "l"(p));
    return a;
}

// pack two fp32 -> bf16x2, v0 in low 16 bits
__device__ __forceinline__ uint32_t bf16x2_pack(float v0, float v1) {
    uint32_t r;
    asm("cvt.rn.bf16x2.f32 %0, %1, %2;" : "=r"(r) : "f"(v1), "f"(v0));
    return r;
}

// fp32 pair -> bf16 hi pair + bf16 residual(lo) pair
__device__ __forceinline__ void split_pair(float v0, float v1, uint32_t& hi, uint32_t& lo) {
    hi = bf16x2_pack(v0, v1);
    float h0 = __uint_as_float(hi << 16);
    float h1 = __uint_as_float(hi & 0xFFFF0000u);
    lo = bf16x2_pack(v0 - h0, v1 - h1);
}

__device__ __forceinline__ void mma16816(float* c, const uint32_t* a, uint32_t b0, uint32_t b1) {
    asm volatile(
        "mma.sync.aligned.m16n8k16.row.col.f32.bf16.bf16.f32 "
        "{%0,%1,%2,%3}, {%4,%5,%6,%7}, {%8,%9}, {%0,%1,%2,%3};"
        : "+f"(c[0]), "+f"(c[1]), "+f"(c[2]), "+f"(c[3])
        : "r"(a[0]), "r"(a[1]), "r"(a[2]), "r"(a[3]), "r"(b0), "r"(b1));
}

__device__ __forceinline__ void cp_async16(uint32_t dst, const void* src) {
    asm volatile("cp.async.cg.shared.global [%0], [%1], 16;" :: "r"(dst), "l"(src) : "memory");
}

// ---------------- prep: weight[lora][k][n] fp32 -> fragment hi/lo scratch ----------------
__global__ void __launch_bounds__(256)
lora_prep_kernel(const float* __restrict__ w) {
    __shared__ float sw[16][68];   // [k_local][n], padded
    const int t = threadIdx.x;
    const float* src = w + (size_t)blockIdx.x * 1024;   // 16 k-rows x 64 n
    float4 v = *(const float4*)(src + t * 4);
    const int kr = t >> 4, nc = (t & 15) * 4;
    sw[kr][nc + 0] = v.x; sw[kr][nc + 1] = v.y;
    sw[kr][nc + 2] = v.z; sw[kr][nc + 3] = v.w;
    __syncthreads();

    const int nt = t >> 5, l = t & 31;
    const int g = l & 3, nl = l >> 2;
    const int n = nt * 8 + nl;
    float v0 = sw[2 * g + 0][n], v1 = sw[2 * g + 1][n];
    float v2 = sw[2 * g + 8][n], v3 = sw[2 * g + 9][n];
    uint32_t h0, l0, h1, l1;
    split_pair(v0, v1, h0, l0);
    split_pair(v2, v3, h1, l1);
    g_wfrag[(size_t)blockIdx.x * 256 + t] = make_uint4(h0, h1, l0, l1);
}

// ---------------- main kernel ----------------
__device__ __forceinline__ void issue_stage(uint32_t sbase, const uint4* wsrc, int s, int t) {
    uint32_t dst = sbase + (uint32_t)(s & 1) * STAGE_BYTES + (uint32_t)t * 16;
    const uint4* src = wsrc + (size_t)s * STAGE_U4 + t;
    #pragma unroll
    for (int j = 0; j < CPS; ++j)
        cp_async16(dst + j * 4096, src + j * 256);
    asm volatile("cp.async.commit_group;" ::: "memory");
}

// A raw loads for one k16 chunk: 8 float2 per thread
// r[2q]   = (row nl + 8q, k0+2g)      r[2q+1] = (row nl + 8q, k0+8+2g)
__device__ __forceinline__ void ldA(const float* p0, int c, float2* r) {
    const float* base = p0 + c * 16;
    #pragma unroll
    for (int q = 0; q < 4; ++q) {
        const float* pp = base + (size_t)q * 8 * D_IN;
        r[2 * q]     = *(const float2*)pp;
        r[2 * q + 1] = *(const float2*)(pp + 8);
    }
}

__global__ void __launch_bounds__(NTHREADS, 2)
lora_main_kernel(const float* __restrict__ x, const int* __restrict__ ids,
                 float* __restrict__ out) {
    extern __shared__ uint4 smem_buf[];
    const uint32_t sbase = smem_u32(smem_buf);
    const int t = threadIdx.x, wid = t >> 5, l = t & 31;
    const int g = l & 3, nl = l >> 2;

    const int b = blockIdx.x >> 3;
    const int mbase = (blockIdx.x & 7) * TILE_M;
    const int aid = __ldg(ids + b);
    const uint4* wsrc = g_wfrag + (size_t)aid * 256 * 256;
    const float* xw = x + ((size_t)b * N_S + mbase + wid * 32) * D_IN;
    const float* p0 = xw + (size_t)nl * D_IN + 2 * g;   // per-thread A base

    float acc[2][8][4];
    #pragma unroll
    for (int mt = 0; mt < 2; ++mt)
        #pragma unroll
        for (int nt = 0; nt < 8; ++nt)
            #pragma unroll
            for (int i = 0; i < 4; ++i)
                acc[mt][nt][i] = 0.0f;

    float2 araw[2][8];
    issue_stage(sbase, wsrc, 0, t);
    ldA(p0, 0, araw[0]);

    for (int c = 0; c < N_KCHUNK; ++c) {
        const int ci = c & 3;
        if (ci == 0) {
            const int s = c >> 2;
            __syncthreads();      // all warps finished reading buffer (s+1)&1 (= stage s-1)
            if (s + 1 < N_STAGE) {
                issue_stage(sbase, wsrc, s + 1, t);
                asm volatile("cp.async.wait_group 1;" ::: "memory");
            } else {
                asm volatile("cp.async.wait_group 0;" ::: "memory");
            }
            __syncthreads();      // stage s visible to every warp
        }

        // prefetch A for next chunk; stays in flight under this chunk's MMAs
        if (c + 1 < N_KCHUNK)
            ldA(p0, c + 1, araw[(c + 1) & 1]);

        // split current chunk's A into bf16 hi/lo fragments
        const float2* r = araw[c & 1];
        uint32_t ah[2][4], al[2][4];
        #pragma unroll
        for (int mt = 0; mt < 2; ++mt) {
            split_pair(r[4 * mt + 0].x, r[4 * mt + 0].y, ah[mt][0], al[mt][0]);
            split_pair(r[4 * mt + 2].x, r[4 * mt + 2].y, ah[mt][1], al[mt][1]);
            split_pair(r[4 * mt + 1].x, r[4 * mt + 1].y, ah[mt][2], al[mt][2]);
            split_pair(r[4 * mt + 3].x, r[4 * mt + 3].y, ah[mt][3], al[mt][3]);
        }

        // B from smem, 3-term mma per (mt, nt)
        const uint32_t stb = sbase + (uint32_t)((c >> 2) & 1) * STAGE_BYTES;
        #pragma unroll
        for (int nt = 0; nt < 8; ++nt) {
            uint32_t bh0, bh1, bl0, bl1;
            uint32_t a = stb + (uint32_t)(((ci * 8 + nt) * 32 + l) * 16);
            asm volatile("ld.shared.v4.b32 {%0,%1,%2,%3}, [%4];"
                         : "=r"(bh0), "=r"(bh1), "=r"(bl0), "=r"(bl1) : "r"(a));
            #pragma unroll
            for (int mt = 0; mt < 2; ++mt) {
                mma16816(acc[mt][nt], ah[mt], bh0, bh1);  // hi * hi
                mma16816(acc[mt][nt], ah[mt], bl0, bl1);  // hi * lo
                mma16816(acc[mt][nt], al[mt], bh0, bh1);  // lo * hi
            }
        }
    }

    // ---- epilogue ----
    #pragma unroll
    for (int mt = 0; mt < 2; ++mt) {
        const int row = mbase + wid * 32 + mt * 16 + nl;
        float* o = out + ((size_t)b * N_S + row) * D_OUT + 2 * g;
        #pragma unroll
        for (int nt = 0; nt < 8; ++nt) {
            *(float2*)(o + nt * 8)             = make_float2(acc[mt][nt][0], acc[mt][nt][1]);
            *(float2*)(o + nt * 8 + 8 * D_OUT) = make_float2(acc[mt][nt][2], acc[mt][nt][3]);
        }
    }
}

// ---------------- launch ----------------
extern "C" void kernel_launch(void* const* d_in, const int* in_sizes, int n_in,
                              void* d_out, int out_size) {
    const float* x  = (const float*)d_in[0];
    const int* ids  = (const int*)d_in[1];
    const float* w  = (const float*)d_in[2];
    float* out      = (float*)d_out;

    lora_prep_kernel<<<N_LORA * 256, 256>>>(w);
    lora_main_kernel<<<N_B * (N_S / TILE_M), NTHREADS, SMEM_TOTAL>>>(x, ids, out);
}

// round 8
// speedup vs baseline: 1.2416x; 1.2416x over previous
#include <cuda_runtime.h>
#include <cuda_bf16.h>
#include <cstdint>

// ---------------- problem constants ----------------
#define D_IN    4096
#define D_OUT   64
#define N_B     32
#define N_S     2048
#define N_LORA  16

#define TILE_M    256
#define NTHREADS  256
#define N_KCHUNK  (D_IN / 16)        // 256 k16 chunks

// ---- smem pipeline: 4 stages, one k16 chunk per stage ----
#define N_STAGES  4
#define A_ROW_B   80                  // 16 floats + 4 pad floats (16B-aligned rows!)
#define A_BYTES   (TILE_M * A_ROW_B)  // 20480
#define B_OFF     A_BYTES
#define B_BYTES   4096                // 256 lanes * uint4
#define STAGE_BYTES (A_BYTES + B_BYTES)       // 24576
#define SMEM_TOTAL  (N_STAGES * STAGE_BYTES)  // 98304 (96 KB)

// ---------------- weight scratch: fragment-layout bf16 hi/lo ----------------
// [lora][kchunk(256)][ntile(8)*32 + lane] -> uint4 {bhi0, bhi1, blo0, blo1}
__device__ __align__(16) uint4 g_wfrag[(size_t)N_LORA * 256 * 256];

// ---------------- helpers ----------------
__device__ __forceinline__ uint32_t smem_u32(const void* p) {
    uint32_t a;
    asm("{ .reg .u64 t; cvta.to.shared.u64 t, %1; cvt.u32.u64 %0, t; }" : "=r"(a) : "l"(p));
    return a;
}

// pack two fp32 -> bf16x2, v0 in low 16 bits
__device__ __forceinline__ uint32_t bf16x2_pack(float v0, float v1) {
    uint32_t r;
    asm("cvt.rn.bf16x2.f32 %0, %1, %2;" : "=r"(r) : "f"(v1), "f"(v0));
    return r;
}

// fp32 pair -> bf16 hi pair + bf16 residual(lo) pair
__device__ __forceinline__ void split_pair(float v0, float v1, uint32_t& hi, uint32_t& lo) {
    hi = bf16x2_pack(v0, v1);
    float h0 = __uint_as_float(hi << 16);
    float h1 = __uint_as_float(hi & 0xFFFF0000u);
    lo = bf16x2_pack(v0 - h0, v1 - h1);
}

__device__ __forceinline__ void mma16816(float* c, const uint32_t* a, uint32_t b0, uint32_t b1) {
    asm volatile(
        "mma.sync.aligned.m16n8k16.row.col.f32.bf16.bf16.f32 "
        "{%0,%1,%2,%3}, {%4,%5,%6,%7}, {%8,%9}, {%0,%1,%2,%3};"
        : "+f"(c[0]), "+f"(c[1]), "+f"(c[2]), "+f"(c[3])
        : "r"(a[0]), "r"(a[1]), "r"(a[2]), "r"(a[3]), "r"(b0), "r"(b1));
}

__device__ __forceinline__ void cp_async16(uint32_t dst, const void* src) {
    asm volatile("cp.async.cg.shared.global [%0], [%1], 16;" :: "r"(dst), "l"(src) : "memory");
}

__device__ __forceinline__ void lds_f2(float2& v, uint32_t a) {
    asm volatile("ld.shared.v2.f32 {%0,%1}, [%2];" : "=f"(v.x), "=f"(v.y) : "r"(a));
}

// ---------------- prep: weight[lora][k][n] fp32 -> fragment hi/lo scratch ----------------
__global__ void __launch_bounds__(256)
lora_prep_kernel(const float* __restrict__ w) {
    __shared__ float sw[16][68];   // [k_local][n], padded
    const int t = threadIdx.x;
    const float* src = w + (size_t)blockIdx.x * 1024;   // 16 k-rows x 64 n
    float4 v = *(const float4*)(src + t * 4);
    const int kr = t >> 4, nc = (t & 15) * 4;
    sw[kr][nc + 0] = v.x; sw[kr][nc + 1] = v.y;
    sw[kr][nc + 2] = v.z; sw[kr][nc + 3] = v.w;
    __syncthreads();

    const int nt = t >> 5, l = t & 31;
    const int g = l & 3, nl = l >> 2;
    const int n = nt * 8 + nl;
    float v0 = sw[2 * g + 0][n], v1 = sw[2 * g + 1][n];
    float v2 = sw[2 * g + 8][n], v3 = sw[2 * g + 9][n];
    uint32_t h0, l0, h1, l1;
    split_pair(v0, v1, h0, l0);
    split_pair(v2, v3, h1, l1);
    g_wfrag[(size_t)blockIdx.x * 256 + t] = make_uint4(h0, h1, l0, l1);
}

// ---------------- main kernel ----------------
// issue one stage: A tile (256 rows x 16 fp32) + B frags (256 uint4) via cp.async
__device__ __forceinline__ void issue_stage(uint32_t sbase, const float* xcta,
                                            const uint4* wsrc, int s, int t) {
    const uint32_t stg = sbase + (uint32_t)(s & (N_STAGES - 1)) * STAGE_BYTES;
    const int r0 = t >> 2, seg = t & 3;
    const float* asrc = xcta + (size_t)r0 * D_IN + s * 16 + seg * 4;
    uint32_t adst = stg + (uint32_t)(r0 * A_ROW_B + seg * 16);
    #pragma unroll
    for (int q = 0; q < 4; ++q)
        cp_async16(adst + q * 64 * A_ROW_B, asrc + (size_t)q * 64 * D_IN);
    cp_async16(stg + B_OFF + (uint32_t)t * 16, wsrc + (size_t)s * 256 + t);
    asm volatile("cp.async.commit_group;" ::: "memory");
}

__global__ void __launch_bounds__(NTHREADS, 2)
lora_main_kernel(const float* __restrict__ x, const int* __restrict__ ids,
                 float* __restrict__ out) {
    extern __shared__ uint4 smem_buf[];
    const uint32_t sbase = smem_u32(smem_buf);
    const int t = threadIdx.x, wid = t >> 5, l = t & 31;
    const int g = l & 3, nl = l >> 2;

    const int b = blockIdx.x >> 3;
    const int mbase = (blockIdx.x & 7) * TILE_M;
    const int aid = __ldg(ids + b);
    const uint4* wsrc = g_wfrag + (size_t)aid * 256 * 256;
    const float* xcta = x + ((size_t)b * N_S + mbase) * D_IN;

    float acc[2][8][4];
    #pragma unroll
    for (int mt = 0; mt < 2; ++mt)
        #pragma unroll
        for (int nt = 0; nt < 8; ++nt)
            #pragma unroll
            for (int i = 0; i < 4; ++i)
                acc[mt][nt][i] = 0.0f;

    // prologue: fill N_STAGES-1 stages
    #pragma unroll
    for (int s = 0; s < N_STAGES - 1; ++s)
        issue_stage(sbase, xcta, wsrc, s, t);

    // per-thread A smem base: row = wid*32 + nl, col = 2g floats
    const uint32_t abase = sbase + (uint32_t)((wid * 32 + nl) * A_ROW_B + g * 8);

    for (int s = 0; s < N_KCHUNK; ++s) {
        asm volatile("cp.async.wait_group %0;" :: "n"(N_STAGES - 2) : "memory");
        __syncthreads();   // stage s visible; all warps done reading stage s-1's buffer
        if (s + N_STAGES - 1 < N_KCHUNK)
            issue_stage(sbase, xcta, wsrc, s + N_STAGES - 1, t);

        const uint32_t stg = (uint32_t)(s & (N_STAGES - 1)) * STAGE_BYTES;

        // ---- A fragments from smem: split fp32 -> bf16 hi/lo ----
        uint32_t ah[2][4], al[2][4];
        #pragma unroll
        for (int mt = 0; mt < 2; ++mt) {
            const uint32_t ab = abase + stg + (uint32_t)(mt * 16 * A_ROW_B);
            float2 f0, f1, f2, f3;
            lds_f2(f0, ab);                         // (row,   k)
            lds_f2(f1, ab + 32);                    // (row,   k+8)
            lds_f2(f2, ab + 8 * A_ROW_B);           // (row+8, k)
            lds_f2(f3, ab + 8 * A_ROW_B + 32);      // (row+8, k+8)
            split_pair(f0.x, f0.y, ah[mt][0], al[mt][0]);
            split_pair(f2.x, f2.y, ah[mt][1], al[mt][1]);
            split_pair(f1.x, f1.y, ah[mt][2], al[mt][2]);
            split_pair(f3.x, f3.y, ah[mt][3], al[mt][3]);
        }

        // ---- B from smem, 3-term mma per (mt, nt) ----
        const uint32_t bb = sbase + stg + B_OFF + (uint32_t)(l * 16);
        #pragma unroll
        for (int nt = 0; nt < 8; ++nt) {
            uint32_t bh0, bh1, bl0, bl1;
            asm volatile("ld.shared.v4.b32 {%0,%1,%2,%3}, [%4];"
                         : "=r"(bh0), "=r"(bh1), "=r"(bl0), "=r"(bl1)
                         : "r"(bb + (uint32_t)(nt * 512)));
            #pragma unroll
            for (int mt = 0; mt < 2; ++mt) {
                mma16816(acc[mt][nt], ah[mt], bh0, bh1);  // hi * hi
                mma16816(acc[mt][nt], ah[mt], bl0, bl1);  // hi * lo
                mma16816(acc[mt][nt], al[mt], bh0, bh1);  // lo * hi
            }
        }
    }

    // ---- epilogue ----
    #pragma unroll
    for (int mt = 0; mt < 2; ++mt) {
        const int row = mbase + wid * 32 + mt * 16 + nl;
        float* o = out + ((size_t)b * N_S + row) * D_OUT + 2 * g;
        #pragma unroll
        for (int nt = 0; nt < 8; ++nt) {
            *(float2*)(o + nt * 8)             = make_float2(acc[mt][nt][0], acc[mt][nt][1]);
            *(float2*)(o + nt * 8 + 8 * D_OUT) = make_float2(acc[mt][nt][2], acc[mt][nt][3]);
        }
    }
}

// ---------------- launch ----------------
extern "C" void kernel_launch(void* const* d_in, const int* in_sizes, int n_in,
                              void* d_out, int out_size) {
    const float* x  = (const float*)d_in[0];
    const int* ids  = (const int*)d_in[1];
    const float* w  = (const float*)d_in[2];
    float* out      = (float*)d_out;

    cudaFuncSetAttribute(lora_main_kernel,
                         cudaFuncAttributeMaxDynamicSharedMemorySize, SMEM_TOTAL);

    lora_prep_kernel<<<N_LORA * 256, 256>>>(w);
    lora_main_kernel<<<N_B * (N_S / TILE_M), NTHREADS, SMEM_TOTAL>>>(x, ids, out);
}

// round 9
// speedup vs baseline: 1.7085x; 1.3761x over previous
#include <cuda_runtime.h>
#include <cuda_bf16.h>
#include <cstdint>

// ---------------- problem constants ----------------
#define D_IN    4096
#define D_OUT   64
#define N_B     32
#define N_S     2048
#define N_LORA  16

#define TILE_M    256
#define NTHREADS  256
#define N_KCHUNK  (D_IN / 16)        // 256 k16 chunks

// ---- smem pipeline: 4 stages, one k16 chunk per stage ----
#define N_STAGES  4
#define A_ROW_B   80                  // 16 floats + 4 pad floats (16B-aligned rows)
#define A_BYTES   (TILE_M * A_ROW_B)  // 20480
#define B_OFF     A_BYTES
#define B_BYTES   4096                // 256 lanes * uint4
#define STAGE_BYTES (A_BYTES + B_BYTES)       // 24576
#define SMEM_TOTAL  (N_STAGES * STAGE_BYTES)  // 98304 (96 KB)

// ---------------- weight scratch: fragment-layout tf32 ----------------
// [lora][kchunk(256)][ntile(8)*32 + lane] -> uint4 {b_k(g), b_k(g+4), b_k(g+8), b_k(g+12)}
// per mma.m16n8k8 B layout: b0 row k = lane&3, b1 row k+4, col n = lane>>2
__device__ __align__(16) uint4 g_wfrag[(size_t)N_LORA * 256 * 256];

// ---------------- helpers ----------------
__device__ __forceinline__ uint32_t smem_u32(const void* p) {
    uint32_t a;
    asm("{ .reg .u64 t; cvta.to.shared.u64 t, %1; cvt.u32.u64 %0, t; }" : "=r"(a) : "l"(p));
    return a;
}

__device__ __forceinline__ uint32_t tf32_rna(float v) {
    uint32_t r;
    asm("cvt.rna.tf32.f32 %0, %1;" : "=r"(r) : "f"(v));
    return r;
}

// m16n8k8 tf32 MMA, fp32 accumulate
__device__ __forceinline__ void mma1688(float* c, const uint32_t* a, uint32_t b0, uint32_t b1) {
    asm volatile(
        "mma.sync.aligned.m16n8k8.row.col.f32.tf32.tf32.f32 "
        "{%0,%1,%2,%3}, {%4,%5,%6,%7}, {%8,%9}, {%0,%1,%2,%3};"
        : "+f"(c[0]), "+f"(c[1]), "+f"(c[2]), "+f"(c[3])
        : "r"(a[0]), "r"(a[1]), "r"(a[2]), "r"(a[3]), "r"(b0), "r"(b1));
}

__device__ __forceinline__ void cp_async16(uint32_t dst, const void* src) {
    asm volatile("cp.async.cg.shared.global [%0], [%1], 16;" :: "r"(dst), "l"(src) : "memory");
}

__device__ __forceinline__ float lds_f32(uint32_t a) {
    float v;
    asm volatile("ld.shared.f32 %0, [%1];" : "=f"(v) : "r"(a));
    return v;
}

// ---------------- prep: weight[lora][k][n] fp32 -> tf32 fragment scratch ----------------
__global__ void __launch_bounds__(256)
lora_prep_kernel(const float* __restrict__ w) {
    __shared__ float sw[16][68];   // [k_local][n], padded
    const int t = threadIdx.x;
    const float* src = w + (size_t)blockIdx.x * 1024;   // 16 k-rows x 64 n
    float4 v = *(const float4*)(src + t * 4);
    const int kr = t >> 4, nc = (t & 15) * 4;
    sw[kr][nc + 0] = v.x; sw[kr][nc + 1] = v.y;
    sw[kr][nc + 2] = v.z; sw[kr][nc + 3] = v.w;
    __syncthreads();

    const int nt = t >> 5, l = t & 31;
    const int g = l & 3, nl = l >> 2;
    const int n = nt * 8 + nl;
    g_wfrag[(size_t)blockIdx.x * 256 + t] = make_uint4(
        tf32_rna(sw[g + 0][n]),  tf32_rna(sw[g + 4][n]),
        tf32_rna(sw[g + 8][n]),  tf32_rna(sw[g + 12][n]));
}

// ---------------- main kernel ----------------
// issue one stage: A tile (256 rows x 16 fp32) + B frags (256 uint4) via cp.async
__device__ __forceinline__ void issue_stage(uint32_t sbase, const float* xcta,
                                            const uint4* wsrc, int s, int t) {
    const uint32_t stg = sbase + (uint32_t)(s & (N_STAGES - 1)) * STAGE_BYTES;
    const int r0 = t >> 2, seg = t & 3;
    const float* asrc = xcta + (size_t)r0 * D_IN + s * 16 + seg * 4;
    uint32_t adst = stg + (uint32_t)(r0 * A_ROW_B + seg * 16);
    #pragma unroll
    for (int q = 0; q < 4; ++q)
        cp_async16(adst + q * 64 * A_ROW_B, asrc + (size_t)q * 64 * D_IN);
    cp_async16(stg + B_OFF + (uint32_t)t * 16, wsrc + (size_t)s * 256 + t);
    asm volatile("cp.async.commit_group;" ::: "memory");
}

__global__ void __launch_bounds__(NTHREADS, 2)
lora_main_kernel(const float* __restrict__ x, const int* __restrict__ ids,
                 float* __restrict__ out) {
    extern __shared__ uint4 smem_buf[];
    const uint32_t sbase = smem_u32(smem_buf);
    const int t = threadIdx.x, wid = t >> 5, l = t & 31;
    const int g = l & 3, nl = l >> 2;

    const int b = blockIdx.x >> 3;
    const int mbase = (blockIdx.x & 7) * TILE_M;
    const int aid = __ldg(ids + b);
    const uint4* wsrc = g_wfrag + (size_t)aid * 256 * 256;
    const float* xcta = x + ((size_t)b * N_S + mbase) * D_IN;

    float acc[2][8][4];
    #pragma unroll
    for (int mt = 0; mt < 2; ++mt)
        #pragma unroll
        for (int nt = 0; nt < 8; ++nt)
            #pragma unroll
            for (int i = 0; i < 4; ++i)
                acc[mt][nt][i] = 0.0f;

    // prologue: fill N_STAGES-1 stages
    #pragma unroll
    for (int s = 0; s < N_STAGES - 1; ++s)
        issue_stage(sbase, xcta, wsrc, s, t);

    // per-thread A smem base: row = wid*32 + nl, col = g floats
    const uint32_t abase = sbase + (uint32_t)((wid * 32 + nl) * A_ROW_B + g * 4);

    for (int s = 0; s < N_KCHUNK; ++s) {
        asm volatile("cp.async.wait_group %0;" :: "n"(N_STAGES - 2) : "memory");
        __syncthreads();   // stage s visible; all warps done reading stage s-1's buffer
        if (s + N_STAGES - 1 < N_KCHUNK)
            issue_stage(sbase, xcta, wsrc, s + N_STAGES - 1, t);

        const uint32_t stg = (uint32_t)(s & (N_STAGES - 1)) * STAGE_BYTES;

        // ---- A fragments from smem: fp32 -> tf32 (rna) ----
        // step0 covers k0..k0+7 (cols g, g+4), step1 covers k0+8..15 (cols g+8, g+12)
        uint32_t a0[2][4], a1[2][4];
        #pragma unroll
        for (int mt = 0; mt < 2; ++mt) {
            const uint32_t ab = abase + stg + (uint32_t)(mt * 16 * A_ROW_B);
            a0[mt][0] = tf32_rna(lds_f32(ab));                        // (row,   g)
            a0[mt][1] = tf32_rna(lds_f32(ab + 8 * A_ROW_B));          // (row+8, g)
            a0[mt][2] = tf32_rna(lds_f32(ab + 16));                   // (row,   g+4)
            a0[mt][3] = tf32_rna(lds_f32(ab + 8 * A_ROW_B + 16));     // (row+8, g+4)
            a1[mt][0] = tf32_rna(lds_f32(ab + 32));                   // (row,   g+8)
            a1[mt][1] = tf32_rna(lds_f32(ab + 8 * A_ROW_B + 32));     // (row+8, g+8)
            a1[mt][2] = tf32_rna(lds_f32(ab + 48));                   // (row,   g+12)
            a1[mt][3] = tf32_rna(lds_f32(ab + 8 * A_ROW_B + 48));     // (row+8, g+12)
        }

        // ---- B from smem, 2 k8-step mma per (mt, nt) ----
        const uint32_t bb = sbase + stg + B_OFF + (uint32_t)(l * 16);
        #pragma unroll
        for (int nt = 0; nt < 8; ++nt) {
            uint32_t b00, b01, b10, b11;
            asm volatile("ld.shared.v4.b32 {%0,%1,%2,%3}, [%4];"
                         : "=r"(b00), "=r"(b01), "=r"(b10), "=r"(b11)
                         : "r"(bb + (uint32_t)(nt * 512)));
            #pragma unroll
            for (int mt = 0; mt < 2; ++mt) {
                mma1688(acc[mt][nt], a0[mt], b00, b01);  // k0..k0+7
                mma1688(acc[mt][nt], a1[mt], b10, b11);  // k0+8..k0+15
            }
        }
    }

    // ---- epilogue ----
    #pragma unroll
    for (int mt = 0; mt < 2; ++mt) {
        const int row = mbase + wid * 32 + mt * 16 + nl;
        float* o = out + ((size_t)b * N_S + row) * D_OUT + 2 * g;
        #pragma unroll
        for (int nt = 0; nt < 8; ++nt) {
            *(float2*)(o + nt * 8)             = make_float2(acc[mt][nt][0], acc[mt][nt][1]);
            *(float2*)(o + nt * 8 + 8 * D_OUT) = make_float2(acc[mt][nt][2], acc[mt][nt][3]);
        }
    }
}

// ---------------- launch ----------------
extern "C" void kernel_launch(void* const* d_in, const int* in_sizes, int n_in,
                              void* d_out, int out_size) {
    const float* x  = (const float*)d_in[0];
    const int* ids  = (const int*)d_in[1];
    const float* w  = (const float*)d_in[2];
    float* out      = (float*)d_out;

    cudaFuncSetAttribute(lora_main_kernel,
                         cudaFuncAttributeMaxDynamicSharedMemorySize, SMEM_TOTAL);

    lora_prep_kernel<<<N_LORA * 256, 256>>>(w);
    lora_main_kernel<<<N_B * (N_S / TILE_M), NTHREADS, SMEM_TOTAL>>>(x, ids, out);
}